// round 1
// baseline (speedup 1.0000x reference)
#include <cuda_runtime.h>
#include <cuda_bf16.h>

#define N_NODES 100000
#define N_EDGES 1600000
#define D 128
#define ALPHA 0.5f
#define TILE_NODES 32
#define W_STRIDE 129
#define N_TILES (N_NODES / TILE_NODES)   // 3125 exactly; 100000 % 32 == 0

// -------- scratch (static device globals; no runtime allocation) --------
__device__ float g_y_src[(size_t)N_NODES * D];   // x @ (alpha*W_src)^T
__device__ float g_y_dst[(size_t)N_NODES * D];   // x @ ((1-alpha)*W_dst)^T
__device__ float g_deg_out[N_NODES];             // degree, then rsqrt in-place
__device__ float g_deg_in[N_NODES];
__device__ int   g_is64;

__device__ __forceinline__ int ldidx(const void* p, long long i, int is64) {
  if (is64) return (int)((const long long*)p)[i];
  return ((const int*)p)[i];
}

// -------- kernel 1: detect index dtype + zero degree arrays --------
__global__ void k_prep(const void* ei) {
  long long i = (long long)blockIdx.x * blockDim.x + threadIdx.x;
  if (i == 0) {
    const long long* p = (const long long*)ei;
    int ok = 1;
#pragma unroll
    for (int j = 0; j < 16; j++) {
      long long v = p[j];
      if (v < 0 || v >= N_NODES) ok = 0;
    }
    g_is64 = ok;   // int32 data interpreted as int64 is out of range w.p. ~1
  }
  if (i < N_NODES) { g_deg_out[i] = 0.f; g_deg_in[i] = 0.f; }
}

// -------- kernel 2: degrees via float atomics --------
__global__ void k_degree(const void* ei) {
  long long e = (long long)blockIdx.x * blockDim.x + threadIdx.x;
  if (e >= N_EDGES) return;
  int is64 = g_is64;
  int r = ldidx(ei, e, is64);
  int c = ldidx(ei, (long long)N_EDGES + e, is64);
  atomicAdd(&g_deg_out[r], 1.f);
  atomicAdd(&g_deg_in[c], 1.f);
}

// -------- kernel 3: deg -> deg^{-1/2} in place --------
__global__ void k_rsqrt() {
  int i = blockIdx.x * blockDim.x + threadIdx.x;
  if (i >= N_NODES) return;
  float d0 = g_deg_out[i];
  float d1 = g_deg_in[i];
  g_deg_out[i] = d0 > 0.f ? rsqrtf(d0) : 0.f;
  g_deg_in[i]  = d1 > 0.f ? rsqrtf(d1) : 0.f;
}

// -------- kernel 4: y_src = x @ (a*Ws)^T, y_dst = x @ ((1-a)*Wd)^T,
//                    out = combined bias (persistent, W cached in smem) --------
__global__ void __launch_bounds__(256, 1) k_transform(
    const float* __restrict__ x,
    const float* __restrict__ W_src, const float* __restrict__ b_src,
    const float* __restrict__ W_dst, const float* __restrict__ b_dst,
    float* __restrict__ out) {
  extern __shared__ float smem[];
  float* Ws = smem;                    // [128][129] transposed (k-major), scaled
  float* Wd = Ws + 128 * W_STRIDE;
  float* xs = Wd + 128 * W_STRIDE;     // [32][128] node-major

  int tid = threadIdx.x;
  for (int idx = tid; idx < D * D; idx += 256) {
    int d = idx >> 7, k = idx & 127;
    Ws[k * W_STRIDE + d] = ALPHA * W_src[idx];          // W[d][k] -> Wt[k][d]
    Wd[k * W_STRIDE + d] = (1.f - ALPHA) * W_dst[idx];
  }
  int d = tid & 127;
  int half = tid >> 7;                  // which 16-node half this thread owns
  float bias = ALPHA * b_src[d] + (1.f - ALPHA) * b_dst[d];
  __syncthreads();

  for (int tile = blockIdx.x; tile < N_TILES; tile += gridDim.x) {
    long long base = (long long)tile * TILE_NODES;
    for (int idx = tid; idx < TILE_NODES * D; idx += 256)
      xs[idx] = x[base * D + idx];
    __syncthreads();

    float acc_s[16], acc_d[16];
#pragma unroll
    for (int i = 0; i < 16; i++) { acc_s[i] = 0.f; acc_d[i] = 0.f; }

    const float* xrow = xs + (half * 16) * D;
#pragma unroll 2
    for (int k = 0; k < D; k++) {
      float ws = Ws[k * W_STRIDE + d];   // conflict-free: bank (k+d)%32
      float wd = Wd[k * W_STRIDE + d];
#pragma unroll
      for (int i = 0; i < 16; i++) {
        float xv = xrow[i * D + k];      // broadcast within warp
        acc_s[i] = fmaf(xv, ws, acc_s[i]);
        acc_d[i] = fmaf(xv, wd, acc_d[i]);
      }
    }

    long long obase = (base + half * 16) * D + d;
#pragma unroll
    for (int i = 0; i < 16; i++) {
      g_y_src[obase + (long long)i * D] = acc_s[i];
      g_y_dst[obase + (long long)i * D] = acc_d[i];
      out[obase + (long long)i * D] = bias;   // init out with combined bias
    }
    __syncthreads();
  }
}

// -------- kernel 5: edge scatter, one warp per edge, float4 reductions --------
__device__ __forceinline__ void red_add_f4(float* p, float a, float b, float c, float d) {
  asm volatile("red.global.add.v4.f32 [%0], {%1, %2, %3, %4};"
               :: "l"(p), "f"(a), "f"(b), "f"(c), "f"(d) : "memory");
}

__global__ void k_scatter(const void* ei, float* __restrict__ out) {
  int lane = threadIdx.x & 31;
  long long e = (long long)blockIdx.x * 8 + (threadIdx.x >> 5);
  if (e >= N_EDGES) return;
  int is64 = g_is64;
  int r = ldidx(ei, e, is64);
  int c = ldidx(ei, (long long)N_EDGES + e, is64);
  float w = g_deg_out[r] * g_deg_in[c];   // dinv_out[row] * dinv_in[col]

  const float4* ys = (const float4*)(g_y_src + (long long)c * D);
  const float4* yd = (const float4*)(g_y_dst + (long long)r * D);
  float4 a = ys[lane];                    // 512B coalesced per warp
  float4 b = yd[lane];

  float* po = out + (long long)r * D + lane * 4;   // out[row] += w * y_src[col]
  red_add_f4(po, w * a.x, w * a.y, w * a.z, w * a.w);
  float* pc = out + (long long)c * D + lane * 4;   // out[col] += w * y_dst[row]
  red_add_f4(pc, w * b.x, w * b.y, w * b.z, w * b.w);
}

// -------- launch --------
extern "C" void kernel_launch(void* const* d_in, const int* in_sizes, int n_in,
                              void* d_out, int out_size) {
  const float* x     = (const float*)d_in[0];
  const void*  ei    = d_in[1];                 // int64 or int32, auto-detected
  const float* W_src = (const float*)d_in[2];
  const float* b_src = (const float*)d_in[3];
  const float* W_dst = (const float*)d_in[4];
  const float* b_dst = (const float*)d_in[5];
  float* out = (float*)d_out;

  k_prep  <<<(N_NODES + 255) / 256, 256>>>(ei);
  k_degree<<<(N_EDGES + 255) / 256, 256>>>(ei);
  k_rsqrt <<<(N_NODES + 255) / 256, 256>>>();

  size_t smem_bytes = (size_t)(2 * 128 * W_STRIDE + TILE_NODES * D) * sizeof(float);
  cudaFuncSetAttribute(k_transform, cudaFuncAttributeMaxDynamicSharedMemorySize,
                       (int)smem_bytes);
  k_transform<<<152, 256, smem_bytes>>>(x, W_src, b_src, W_dst, b_dst, out);

  k_scatter<<<N_EDGES / 8, 256>>>(ei, out);   // 1.6M % 8 == 0
}